// round 5
// baseline (speedup 1.0000x reference)
#include <cuda_runtime.h>
#include <math.h>
#include <stdint.h>

#define NUM_CLASSES 10
#define PV 15                         // floats per cell
#define THREADS 128
#define TILE_CELLS 128
#define TILE_F4 (TILE_CELLS * PV / 4) // 480 float4 per array per tile
#define TOTAL_CELLS (2048 * 26 * 26)  // 1,384,448
#define NTILES (TOTAL_CELLS / TILE_CELLS) // 10816 (exact)
#define STAGES 3
#define GRID 592                      // 148 SMs * 4 CTAs (45KB smem each)
#define LAMBDA_COORD 5.0f
#define LAMBDA_NOOBJ 0.5f

// Global state: accumulators + completion counter + work-stealing tile counter.
// Zero at module load; reset by the finalizing block each call (graph-replay safe).
__device__ double g_acc[3];
__device__ unsigned int g_count;
__device__ unsigned int g_tile;

__device__ __forceinline__ void cp16(uint32_t s, const float4* g) {
    asm volatile("cp.async.cg.shared.global [%0], [%1], 16;" :: "r"(s), "l"(g));
}
#define CP_COMMIT() asm volatile("cp.async.commit_group;" ::: "memory")
#define CP_WAIT2()  asm volatile("cp.async.wait_group 2;"  ::: "memory")

__global__ __launch_bounds__(THREADS)
void yolo_fused_kernel(const float* __restrict__ pred,
                       const float* __restrict__ tgt,
                       float* __restrict__ out) {
    // [stage][0]=pred tile, [stage][1]=tgt tile
    __shared__ float4 sbuf[STAGES][2][TILE_F4];        // 46080 B
    __shared__ unsigned int s_tile[8];                 // ring of fetched tile ids
    __shared__ float red[3][THREADS / 32];
    __shared__ bool s_is_last;

    const int tid = threadIdx.x;
    const uint32_t sbase = (uint32_t)__cvta_generic_to_shared(&sbuf[0][0][0]);
    const float4* pred4 = (const float4*)pred;
    const float4* tgt4  = (const float4*)tgt;

    float acc0 = 0.0f, acc1 = 0.0f, acc2 = 0.0f;

    // ---- Prologue: fetch + issue STAGES tiles ----
    #pragma unroll
    for (int s = 0; s < STAGES; s++) {
        if (tid == 0) s_tile[s] = atomicAdd(&g_tile, 1u);
        __syncthreads();
        unsigned int tt = s_tile[s];
        if (tt < (unsigned int)NTILES) {
            const float4* p4 = pred4 + (size_t)tt * TILE_F4;
            const float4* t4 = tgt4  + (size_t)tt * TILE_F4;
            const uint32_t bp = sbase + (uint32_t)(s * 2 * TILE_F4) * 16u;
            const uint32_t bt = bp + (uint32_t)TILE_F4 * 16u;
            for (int i = tid; i < TILE_F4; i += THREADS) {
                cp16(bp + (uint32_t)i * 16u, p4 + i);
                cp16(bt + (uint32_t)i * 16u, t4 + i);
            }
        }
        CP_COMMIT();
    }

    // ---- Main loop ----
    int k = 0;
    while (true) {
        unsigned int cur = s_tile[k & 7];
        if (cur >= (unsigned int)NTILES) break;

        CP_WAIT2();            // stage (k % STAGES) data complete (this thread's)
        __syncthreads();       // ... and visible block-wide

        // Fetch the tile that will refill this stage (overlaps with compute).
        if (tid == 0) s_tile[(k + STAGES) & 7] = atomicAdd(&g_tile, 1u);

        // Compute: one cell per thread from SMEM (stride-15, conflict-free).
        const int st = k % STAGES;
        const float* p = (const float*)&sbuf[st][0][0] + tid * PV;
        const float* q = (const float*)&sbuf[st][1][0] + tid * PV;

        float t_conf = q[4];
        bool  obj    = t_conf > 0.0f;

        float coord_sq = 0.0f;
        #pragma unroll
        for (int j = 0; j < 4; j++) {
            float d = p[j] - q[j];
            coord_sq += d * d;
        }

        float conf_p = 1.0f / (1.0f + __expf(-p[4]));

        float cls_sq = 0.0f;
        #pragma unroll
        for (int j = 5; j < 5 + NUM_CLASSES; j++) {
            float d = p[j] - q[j];
            cls_sq += d * d;
        }
        cls_sq *= (1.0f / (float)NUM_CLASSES);

        float dconf = conf_p - t_conf;
        acc0 += obj ? LAMBDA_COORD * coord_sq : 0.0f;
        acc1 += obj ? dconf * dconf : LAMBDA_NOOBJ * conf_p * conf_p;
        acc2 += obj ? cls_sq : 0.0f;

        __syncthreads();       // buffer free + fetched tile id visible

        unsigned int nt = s_tile[(k + STAGES) & 7];
        if (nt < (unsigned int)NTILES) {
            const float4* p4 = pred4 + (size_t)nt * TILE_F4;
            const float4* t4 = tgt4  + (size_t)nt * TILE_F4;
            const uint32_t bp = sbase + (uint32_t)(st * 2 * TILE_F4) * 16u;
            const uint32_t bt = bp + (uint32_t)TILE_F4 * 16u;
            for (int i = tid; i < TILE_F4; i += THREADS) {
                cp16(bp + (uint32_t)i * 16u, p4 + i);
                cp16(bt + (uint32_t)i * 16u, t4 + i);
            }
        }
        CP_COMMIT();
        k++;
    }

    // ---- Block reduction ----
    #pragma unroll
    for (int off = 16; off > 0; off >>= 1) {
        acc0 += __shfl_xor_sync(0xFFFFFFFFu, acc0, off);
        acc1 += __shfl_xor_sync(0xFFFFFFFFu, acc1, off);
        acc2 += __shfl_xor_sync(0xFFFFFFFFu, acc2, off);
    }
    const int lane = tid & 31;
    const int wid  = tid >> 5;
    if (lane == 0) {
        red[0][wid] = acc0;
        red[1][wid] = acc1;
        red[2][wid] = acc2;
    }
    __syncthreads();

    if (tid == 0) {
        float a = 0.0f, b = 0.0f, c = 0.0f;
        #pragma unroll
        for (int w = 0; w < THREADS / 32; w++) {
            a += red[0][w]; b += red[1][w]; c += red[2][w];
        }
        atomicAdd(&g_acc[0], (double)a);
        atomicAdd(&g_acc[1], (double)b);
        atomicAdd(&g_acc[2], (double)c);
        __threadfence();
        unsigned int prev = atomicAdd(&g_count, 1u);
        s_is_last = (prev == (unsigned int)(GRID - 1));
    }
    __syncthreads();

    // ---- Last block: finalize output, reset all state for next replay ----
    if (s_is_last && tid == 0) {
        volatile double* acc = g_acc;
        double c = acc[0], f = acc[1], l = acc[2];
        out[0] = (float)(c + f + l);   // total
        out[1] = (float)c;             // coord
        out[2] = (float)f;             // conf
        out[3] = (float)l;             // class
        g_acc[0] = 0.0;
        g_acc[1] = 0.0;
        g_acc[2] = 0.0;
        g_count  = 0u;
        g_tile   = 0u;
    }
}

extern "C" void kernel_launch(void* const* d_in, const int* in_sizes, int n_in,
                              void* d_out, int out_size) {
    const float* pred = (const float*)d_in[0];
    const float* tgt  = (const float*)d_in[1];
    float* out = (float*)d_out;

    yolo_fused_kernel<<<GRID, THREADS>>>(pred, tgt, out);
}

// round 6
// speedup vs baseline: 1.1880x; 1.1880x over previous
#include <cuda_runtime.h>
#include <math.h>
#include <stdint.h>

#define NUM_CLASSES 10
#define PV 15                         // floats per cell
#define THREADS 128
#define TILE_CELLS 128
#define TILE_F4 (TILE_CELLS * PV / 4) // 480 float4 per array per tile
#define TOTAL_CELLS (2048 * 26 * 26)  // 1,384,448
#define NTILES (TOTAL_CELLS / TILE_CELLS) // 10816 (exact)
#define STAGES 3
#define GRID 592                      // 148 SMs * 4 CTAs (46KB smem each)
#define LAMBDA_COORD 5.0f
#define LAMBDA_NOOBJ 0.5f

// Accumulators + completion counter. Zero at module load; reset by the
// finalizing block each call (graph-replay safe).
__device__ double g_acc[3];
__device__ unsigned int g_count;

__device__ __forceinline__ void cp16(uint32_t s, const float4* g) {
    asm volatile("cp.async.cg.shared.global [%0], [%1], 16;" :: "r"(s), "l"(g));
}
#define CP_COMMIT() asm volatile("cp.async.commit_group;" ::: "memory")
#define CP_WAIT2()  asm volatile("cp.async.wait_group 2;"  ::: "memory")

// Issue one tile's loads into a stage (no-op if tile out of range).
__device__ __forceinline__ void issue_tile(const float4* pred4, const float4* tgt4,
                                           uint32_t sbase, int stage, long long tile,
                                           int tid) {
    if (tile < (long long)NTILES) {
        const float4* p4 = pred4 + (size_t)tile * TILE_F4;
        const float4* t4 = tgt4  + (size_t)tile * TILE_F4;
        const uint32_t bp = sbase + (uint32_t)(stage * 2 * TILE_F4) * 16u;
        const uint32_t bt = bp + (uint32_t)TILE_F4 * 16u;
        #pragma unroll 4
        for (int i = tid; i < TILE_F4; i += THREADS) {
            cp16(bp + (uint32_t)i * 16u, p4 + i);
            cp16(bt + (uint32_t)i * 16u, t4 + i);
        }
    }
}

__global__ __launch_bounds__(THREADS)
void yolo_fused_kernel(const float* __restrict__ pred,
                       const float* __restrict__ tgt,
                       float* __restrict__ out) {
    // [stage][0]=pred tile, [stage][1]=tgt tile
    __shared__ float4 sbuf[STAGES][2][TILE_F4];   // 46080 B
    __shared__ float red[3][THREADS / 32];
    __shared__ bool s_is_last;

    const int tid = threadIdx.x;
    const uint32_t sbase = (uint32_t)__cvta_generic_to_shared(&sbuf[0][0][0]);
    const float4* pred4 = (const float4*)pred;
    const float4* tgt4  = (const float4*)tgt;

    float acc0 = 0.0f, acc1 = 0.0f, acc2 = 0.0f;

    // ---- Prologue: issue STAGES tiles (static cyclic schedule) ----
    #pragma unroll
    for (int s = 0; s < STAGES; s++) {
        issue_tile(pred4, tgt4, sbase, s,
                   (long long)blockIdx.x + (long long)s * GRID, tid);
        CP_COMMIT();
    }

    // ---- Main loop: tile k is waited on ~2 iterations after issue ----
    long long t = blockIdx.x;
    for (int k = 0; t < NTILES; t += GRID, k++) {
        CP_WAIT2();            // group k complete -> stage (k%3) data ready
        __syncthreads();       // visible block-wide

        const int st = k % STAGES;
        const float* p = (const float*)&sbuf[st][0][0] + tid * PV;
        const float* q = (const float*)&sbuf[st][1][0] + tid * PV;

        float t_conf = q[4];
        bool  obj    = t_conf > 0.0f;

        float coord_sq = 0.0f;
        #pragma unroll
        for (int j = 0; j < 4; j++) {
            float d = p[j] - q[j];
            coord_sq += d * d;
        }

        float conf_p = 1.0f / (1.0f + __expf(-p[4]));

        float cls_sq = 0.0f;
        #pragma unroll
        for (int j = 5; j < 5 + NUM_CLASSES; j++) {
            float d = p[j] - q[j];
            cls_sq += d * d;
        }
        cls_sq *= (1.0f / (float)NUM_CLASSES);

        float dconf = conf_p - t_conf;
        acc0 += obj ? LAMBDA_COORD * coord_sq : 0.0f;
        acc1 += obj ? dconf * dconf : LAMBDA_NOOBJ * conf_p * conf_p;
        acc2 += obj ? cls_sq : 0.0f;

        __syncthreads();       // all reads done before this stage is refilled

        // Refill this stage with tile k+STAGES (empty commit keeps group
        // accounting consistent when out of range).
        issue_tile(pred4, tgt4, sbase, st, t + (long long)STAGES * GRID, tid);
        CP_COMMIT();
    }

    // ---- Block reduction ----
    #pragma unroll
    for (int off = 16; off > 0; off >>= 1) {
        acc0 += __shfl_xor_sync(0xFFFFFFFFu, acc0, off);
        acc1 += __shfl_xor_sync(0xFFFFFFFFu, acc1, off);
        acc2 += __shfl_xor_sync(0xFFFFFFFFu, acc2, off);
    }
    const int lane = tid & 31;
    const int wid  = tid >> 5;
    if (lane == 0) {
        red[0][wid] = acc0;
        red[1][wid] = acc1;
        red[2][wid] = acc2;
    }
    __syncthreads();

    if (tid == 0) {
        float a = 0.0f, b = 0.0f, c = 0.0f;
        #pragma unroll
        for (int w = 0; w < THREADS / 32; w++) {
            a += red[0][w]; b += red[1][w]; c += red[2][w];
        }
        atomicAdd(&g_acc[0], (double)a);
        atomicAdd(&g_acc[1], (double)b);
        atomicAdd(&g_acc[2], (double)c);
        __threadfence();
        unsigned int prev = atomicAdd(&g_count, 1u);
        s_is_last = (prev == (unsigned int)(GRID - 1));
    }
    __syncthreads();

    // ---- Last block: finalize output, reset state for next replay ----
    if (s_is_last && tid == 0) {
        volatile double* acc = g_acc;
        double c = acc[0], f = acc[1], l = acc[2];
        out[0] = (float)(c + f + l);   // total
        out[1] = (float)c;             // coord
        out[2] = (float)f;             // conf
        out[3] = (float)l;             // class
        g_acc[0] = 0.0;
        g_acc[1] = 0.0;
        g_acc[2] = 0.0;
        g_count  = 0u;
    }
}

extern "C" void kernel_launch(void* const* d_in, const int* in_sizes, int n_in,
                              void* d_out, int out_size) {
    const float* pred = (const float*)d_in[0];
    const float* tgt  = (const float*)d_in[1];
    float* out = (float*)d_out;

    yolo_fused_kernel<<<GRID, THREADS>>>(pred, tgt, out);
}